// round 1
// baseline (speedup 1.0000x reference)
#include <cuda_runtime.h>
#include <cuda_bf16.h>
#include <math.h>

// Problem constants
#define BB 4
#define TT 2048
#define CC 2048
#define HH 16
#define HD 128
#define NTOK (BB*TT)          // 8192
#define C4 (4*CC)             // 8192
#define QKVN (3*CC)           // 6144

// ---------------- scratch (device globals; no allocation allowed) ------------
__device__ float g_h1  [(size_t)NTOK * CC];     // ln1 out
__device__ float g_qkv [(size_t)NTOK * QKVN];   // q|k|v concat, col = s*2048 + h*128 + d
__device__ float g_attn[(size_t)NTOK * CC];     // attention out (heads concat)
__device__ float g_x1  [(size_t)NTOK * CC];     // x + proj
__device__ float g_h2  [(size_t)NTOK * CC];     // ln2 out
__device__ float g_ffn [(size_t)NTOK * C4];     // gelu(h2@W1+b1)
__device__ float g_wqkv[(size_t)CC * QKVN];     // packed qkv weights [C, 3C]

// ---------------- layernorm ---------------------------------------------------
__global__ void ln_kernel(const float* __restrict__ x, const float* __restrict__ g,
                          const float* __restrict__ beta, float* __restrict__ out) {
    int t = blockIdx.x;
    const float* xr = x + (size_t)t * CC;
    float* orow = out + (size_t)t * CC;
    float s = 0.f, s2 = 0.f;
    for (int i = threadIdx.x; i < CC; i += 256) { float v = xr[i]; s += v; s2 += v * v; }
    __shared__ float red0[8], red1[8];
    #pragma unroll
    for (int o = 16; o; o >>= 1) {
        s  += __shfl_xor_sync(0xffffffffu, s,  o);
        s2 += __shfl_xor_sync(0xffffffffu, s2, o);
    }
    int w = threadIdx.x >> 5, l = threadIdx.x & 31;
    if (l == 0) { red0[w] = s; red1[w] = s2; }
    __syncthreads();
    if (w == 0) {
        s  = (l < 8) ? red0[l] : 0.f;
        s2 = (l < 8) ? red1[l] : 0.f;
        #pragma unroll
        for (int o = 4; o; o >>= 1) {
            s  += __shfl_xor_sync(0xffffffffu, s,  o);
            s2 += __shfl_xor_sync(0xffffffffu, s2, o);
        }
        if (l == 0) { red0[0] = s; red1[0] = s2; }
    }
    __syncthreads();
    float mean = red0[0] * (1.f / CC);
    float var  = red1[0] * (1.f / CC) - mean * mean;
    float rstd = rsqrtf(var + 1e-5f);
    for (int i = threadIdx.x; i < CC; i += 256)
        orow[i] = (xr[i] - mean) * rstd * g[i] + beta[i];
}

// ---------------- pack Wq/Wk/Wv -> [C, 3C] ------------------------------------
__global__ void pack_qkv_kernel(const float* __restrict__ Wq, const float* __restrict__ Wk,
                                const float* __restrict__ Wv, float* __restrict__ Wcat) {
    int idx = blockIdx.x * blockDim.x + threadIdx.x;   // (s, h, c, d)
    if (idx >= 3 * CC * CC) return;
    int d = idx & 127;
    int c = (idx >> 7) & 2047;
    int h = (idx >> 18) & 15;
    int s = idx >> 22;
    const float* W = (s == 0) ? Wq : (s == 1) ? Wk : Wv;
    Wcat[(size_t)c * QKVN + s * CC + h * HD + d] = W[((size_t)h * CC + c) * HD + d];
}

// ---------------- generic GEMM ------------------------------------------------
__device__ __forceinline__ float gelu_exact(float v) {
    return 0.5f * v * (1.0f + erff(v * 0.7071067811865475f));
}

template<bool BIAS, bool RES, bool GELU>
__global__ __launch_bounds__(256)
void gemm_kernel(const float* __restrict__ A, const float* __restrict__ B,
                 const float* __restrict__ bias, const float* __restrict__ res,
                 float* __restrict__ C, int M, int N, int K) {
    __shared__ float As[8][132];   // As[k][m], padded
    __shared__ float Bs[8][128];

    const int tid = threadIdx.x;
    const int bm = blockIdx.y * 128;
    const int bn = blockIdx.x * 128;

    const int a_row = tid >> 1;
    const int a_col = (tid & 1) * 4;
    const int b_row = tid >> 5;
    const int b_col = (tid & 31) * 4;

    const float* Aptr = A + (size_t)(bm + a_row) * K + a_col;
    const float* Bptr = B + (size_t)b_row * N + bn + b_col;

    const int tx = tid & 15, ty = tid >> 4;
    const int cm = ty * 8, cn = tx * 8;

    float acc[8][8];
    #pragma unroll
    for (int i = 0; i < 8; i++)
        #pragma unroll
        for (int j = 0; j < 8; j++) acc[i][j] = 0.f;

    for (int k0 = 0; k0 < K; k0 += 8) {
        float4 av = *(const float4*)Aptr;
        float4 bv = *(const float4*)Bptr;
        __syncthreads();
        As[a_col + 0][a_row] = av.x;
        As[a_col + 1][a_row] = av.y;
        As[a_col + 2][a_row] = av.z;
        As[a_col + 3][a_row] = av.w;
        *(float4*)&Bs[b_row][b_col] = bv;
        __syncthreads();
        #pragma unroll
        for (int kk = 0; kk < 8; kk++) {
            float a[8], b[8];
            *(float4*)(a)     = *(const float4*)&As[kk][cm];
            *(float4*)(a + 4) = *(const float4*)&As[kk][cm + 4];
            *(float4*)(b)     = *(const float4*)&Bs[kk][cn];
            *(float4*)(b + 4) = *(const float4*)&Bs[kk][cn + 4];
            #pragma unroll
            for (int i = 0; i < 8; i++)
                #pragma unroll
                for (int j = 0; j < 8; j++) acc[i][j] += a[i] * b[j];
        }
        Aptr += 8;
        Bptr += (size_t)8 * N;
    }

    #pragma unroll
    for (int i = 0; i < 8; i++) {
        size_t off = (size_t)(bm + cm + i) * N + bn + cn;
        #pragma unroll
        for (int j0 = 0; j0 < 8; j0 += 4) {
            float4 v;
            v.x = acc[i][j0 + 0]; v.y = acc[i][j0 + 1];
            v.z = acc[i][j0 + 2]; v.w = acc[i][j0 + 3];
            if (BIAS) {
                float4 bb = *(const float4*)&bias[bn + cn + j0];
                v.x += bb.x; v.y += bb.y; v.z += bb.z; v.w += bb.w;
            }
            if (GELU) {
                v.x = gelu_exact(v.x); v.y = gelu_exact(v.y);
                v.z = gelu_exact(v.z); v.w = gelu_exact(v.w);
            }
            if (RES) {
                float4 rr = *(const float4*)&res[off + j0];
                v.x += rr.x; v.y += rr.y; v.z += rr.z; v.w += rr.w;
            }
            *(float4*)&C[off + j0] = v;
        }
    }
}

// ---------------- causal flash attention --------------------------------------
// block: 128 threads, 64-query tile; grid (T/64, B*H)
__global__ __launch_bounds__(128)
void attention_kernel(const float* __restrict__ qkv, float* __restrict__ out) {
    extern __shared__ float sm[];
    float* Qt  = sm;               // [128][65]  (d-major, padded)
    float* Kt  = Qt + 128 * 65;    // [128][65]
    float* Vs  = Kt + 128 * 65;    // [64][128]
    float* Ss  = Vs + 64 * 128;    // [64][65]
    float* m_s = Ss + 64 * 65;     // [64]
    float* l_s = m_s + 64;         // [64]
    float* c_s = l_s + 64;         // [64]

    const int tid = threadIdx.x;
    const int bh = blockIdx.y;
    const int b  = bh >> 4, h = bh & 15;
    const int qb = blockIdx.x;
    const int q0 = qb * 64;
    const float scale = 0.08838834764831845f;   // 1/sqrt(128)

    const size_t base = ((size_t)b * TT) * QKVN + h * HD;

    for (int idx = tid; idx < 64 * 128; idx += 128) {
        int r = idx >> 7, d = idx & 127;
        Qt[d * 65 + r] = qkv[base + (size_t)(q0 + r) * QKVN + d] * scale;
    }
    if (tid < 64) { m_s[tid] = -1e30f; l_s[tid] = 0.f; }

    float O[4][16];
    #pragma unroll
    for (int i = 0; i < 4; i++)
        #pragma unroll
        for (int n = 0; n < 16; n++) O[i][n] = 0.f;

    const int ty = tid >> 3, tx = tid & 7;
    const int r0 = ty * 4;

    for (int kb = 0; kb <= qb; kb++) {
        const int k0 = kb * 64;
        __syncthreads();   // protect Kt/Vs/Ss from previous iteration readers
        for (int idx = tid; idx < 64 * 128; idx += 128) {
            int c = idx >> 7, d = idx & 127;
            size_t tk = base + (size_t)(k0 + c) * QKVN;
            Kt[d * 65 + c]  = qkv[tk + CC + d];         // K
            Vs[c * 128 + d] = qkv[tk + 2 * CC + d];     // V
        }
        __syncthreads();

        // S = Q K^T   (rows r0..r0+3, cols tx + 8j)
        float sacc[4][8];
        #pragma unroll
        for (int i = 0; i < 4; i++)
            #pragma unroll
            for (int j = 0; j < 8; j++) sacc[i][j] = 0.f;
        #pragma unroll 4
        for (int d = 0; d < 128; d++) {
            float a[4], kv[8];
            #pragma unroll
            for (int i = 0; i < 4; i++) a[i] = Qt[d * 65 + r0 + i];
            #pragma unroll
            for (int j = 0; j < 8; j++) kv[j] = Kt[d * 65 + tx + 8 * j];
            #pragma unroll
            for (int i = 0; i < 4; i++)
                #pragma unroll
                for (int j = 0; j < 8; j++) sacc[i][j] += a[i] * kv[j];
        }
        const bool diag = (kb == qb);
        #pragma unroll
        for (int i = 0; i < 4; i++)
            #pragma unroll
            for (int j = 0; j < 8; j++) {
                int r = r0 + i, c = tx + 8 * j;
                float v = sacc[i][j];
                if (diag && c > r) v = -1e30f;
                Ss[r * 65 + c] = v;
            }
        __syncthreads();

        // online softmax, 1 thread per row
        if (tid < 64) {
            int r = tid;
            float mold = m_s[r];
            float mx = mold;
            for (int c = 0; c < 64; c++) mx = fmaxf(mx, Ss[r * 65 + c]);
            float corr = __expf(mold - mx);
            float sum = 0.f;
            for (int c = 0; c < 64; c++) {
                float p = __expf(Ss[r * 65 + c] - mx);
                Ss[r * 65 + c] = p;
                sum += p;
            }
            m_s[r] = mx;
            l_s[r] = l_s[r] * corr + sum;
            c_s[r] = corr;
        }
        __syncthreads();

        // O = O*corr + P V   (cols d = tx*4 + 32*jj + u)
        float cr[4];
        #pragma unroll
        for (int i = 0; i < 4; i++) cr[i] = c_s[r0 + i];
        #pragma unroll
        for (int i = 0; i < 4; i++)
            #pragma unroll
            for (int n = 0; n < 16; n++) O[i][n] *= cr[i];
        #pragma unroll 2
        for (int c = 0; c < 64; c++) {
            float a[4];
            #pragma unroll
            for (int i = 0; i < 4; i++) a[i] = Ss[(r0 + i) * 65 + c];
            float vv[16];
            #pragma unroll
            for (int jj = 0; jj < 4; jj++)
                *(float4*)&vv[jj * 4] = *(const float4*)&Vs[c * 128 + tx * 4 + 32 * jj];
            #pragma unroll
            for (int i = 0; i < 4; i++)
                #pragma unroll
                for (int n = 0; n < 16; n++) O[i][n] += a[i] * vv[n];
        }
    }

    float li[4];
    #pragma unroll
    for (int i = 0; i < 4; i++) li[i] = 1.f / l_s[r0 + i];
    const size_t obase = ((size_t)b * TT) * CC + h * HD;
    #pragma unroll
    for (int i = 0; i < 4; i++) {
        size_t rowoff = obase + (size_t)(q0 + r0 + i) * CC;
        #pragma unroll
        for (int jj = 0; jj < 4; jj++) {
            float4 v;
            v.x = O[i][jj * 4 + 0] * li[i];
            v.y = O[i][jj * 4 + 1] * li[i];
            v.z = O[i][jj * 4 + 2] * li[i];
            v.w = O[i][jj * 4 + 3] * li[i];
            *(float4*)&out[rowoff + tx * 4 + 32 * jj] = v;
        }
    }
}

// ---------------- host launcher -----------------------------------------------
extern "C" void kernel_launch(void* const* d_in, const int* in_sizes, int n_in,
                              void* d_out, int out_size) {
    const float* x     = (const float*)d_in[0];
    const float* Wq    = (const float*)d_in[1];
    const float* Wk    = (const float*)d_in[2];
    const float* Wv    = (const float*)d_in[3];
    const float* Wp    = (const float*)d_in[4];
    const float* bp    = (const float*)d_in[5];
    const float* W1    = (const float*)d_in[6];
    const float* b1    = (const float*)d_in[7];
    const float* W2    = (const float*)d_in[8];
    const float* b2    = (const float*)d_in[9];
    const float* g1    = (const float*)d_in[10];
    const float* beta1 = (const float*)d_in[11];
    const float* g2    = (const float*)d_in[12];
    const float* beta2 = (const float*)d_in[13];
    float* out = (float*)d_out;

    float *h1, *qkv, *attn, *x1, *h2, *ffn, *wqkv;
    cudaGetSymbolAddress((void**)&h1,   g_h1);
    cudaGetSymbolAddress((void**)&qkv,  g_qkv);
    cudaGetSymbolAddress((void**)&attn, g_attn);
    cudaGetSymbolAddress((void**)&x1,   g_x1);
    cudaGetSymbolAddress((void**)&h2,   g_h2);
    cudaGetSymbolAddress((void**)&ffn,  g_ffn);
    cudaGetSymbolAddress((void**)&wqkv, g_wqkv);

    const int attn_smem = (128 * 65 * 2 + 64 * 128 + 64 * 65 + 192) * 4;  // 116736 B
    cudaFuncSetAttribute(attention_kernel,
                         cudaFuncAttributeMaxDynamicSharedMemorySize, attn_smem);

    // 1. LN1
    ln_kernel<<<NTOK, 256>>>(x, g1, beta1, h1);
    // 2. pack qkv weights
    pack_qkv_kernel<<<(3 * CC * CC + 255) / 256, 256>>>(Wq, Wk, Wv, wqkv);
    // 3. QKV gemm  [8192, 2048] x [2048, 6144]
    gemm_kernel<false, false, false><<<dim3(QKVN / 128, NTOK / 128), 256>>>(
        h1, wqkv, nullptr, nullptr, qkv, NTOK, QKVN, CC);
    // 4. attention
    attention_kernel<<<dim3(TT / 64, BB * HH), 128, attn_smem>>>(qkv, attn);
    // 5. proj: x1 = x + attn @ Wp + bp
    gemm_kernel<true, true, false><<<dim3(CC / 128, NTOK / 128), 256>>>(
        attn, Wp, bp, x, x1, NTOK, CC, CC);
    // 6. LN2
    ln_kernel<<<NTOK, 256>>>(x1, g2, beta2, h2);
    // 7. FFN1: ffn = gelu(h2 @ W1 + b1)
    gemm_kernel<true, false, true><<<dim3(C4 / 128, NTOK / 128), 256>>>(
        h2, W1, b1, nullptr, ffn, NTOK, C4, CC);
    // 8. FFN2: out = x1 + ffn @ W2 + b2
    gemm_kernel<true, true, false><<<dim3(CC / 128, NTOK / 128), 256>>>(
        ffn, W2, b2, x1, out, NTOK, CC, C4);
}